// round 12
// baseline (speedup 1.0000x reference)
#include <cuda_runtime.h>
#include <cuda_bf16.h>
#include <stdint.h>

// Problem constants
#define NB      32
#define NN      64
#define MV      2080          // NN*(NN+1)/2 = 65*32
#define MAIN    2048
#define NEXTRA  32
#define TOPK    5
#define NEIGHBOR 16
#define NEGATIVE 16
#define TOTAL   85            // TOPK*(NEIGHBOR+1)
#define KOUT    101           // NEGATIVE + TOTAL
#define DFEAT   512
#define NT      544           // 16 sorter warps + 1 extras warp

// dynamic smem layout (byte offsets)
#define OFF_FKEY    0          // u64[2080]  16640
#define OFF_MKEY    16640      // u64[2048]  16384
#define OFF_EXTRA   33024      // u64[32]      256
#define OFF_MOM     33280      // u32[2080]   8320
#define OFF_RR      41600      // u8[2080]    2080
#define OFF_CC      43680      // u8[2080]    2080
#define OFF_UNSUP   45760      // u16[2080]   4160
#define OFF_SELIDX  49920      // u16[96]      192
#define OFF_WSUM    50112      // int[40]      160
#define OFF_FR      50272      // int[101]     404
#define OFF_FC      50676      // int[101]     404
#define OFF_SUPW    51080      // u32[65]      260
#define OFF_SELW    51344      // u32[65]      260
#define SMEM_BYTES  51712

typedef unsigned long long u64;

__device__ __forceinline__ void cas64(u64& a, u64& b, bool dir) {
    u64 x = a, y = b;
    bool sw = dir ? (x < y) : (x > y);
    a = sw ? y : x;
    b = sw ? x : y;
}

template<int J0>
__device__ __forceinline__ void reg_stages(u64 e[4], int tid, int lane, int k) {
    const int base = tid * 4;
    const bool dirU = ((base & k) == 0);
#pragma unroll
    for (int j = J0; j >= 4; j >>= 1) {
        int lm = j >> 2;
        bool lower = ((lane & lm) == 0);
        bool keepMax = (lower == dirU);
#pragma unroll
        for (int v = 0; v < 4; v++) {
            u64 p = __shfl_xor_sync(0xffffffffu, e[v], lm);
            u64 mx = e[v] > p ? e[v] : p;
            u64 mn = e[v] > p ? p : e[v];
            e[v] = keepMax ? mx : mn;
        }
    }
    if (J0 >= 2) {
        cas64(e[0], e[2], dirU);
        cas64(e[1], e[3], dirU);
    }
    if (k == 2) {
        cas64(e[0], e[1], true);
        cas64(e[2], e[3], false);
    } else {
        cas64(e[0], e[1], dirU);
        cas64(e[2], e[3], dirU);
    }
}

// Two levels (2j, j) of merge k over 2048 elems; 512 sorter threads.
__device__ __forceinline__ void pass2(u64* a, int k, int j, int lg, int tid) {
    int low  = tid & (j - 1);
    int hi   = tid >> lg;
    int base = (hi << (lg + 2)) | low;
    u64 e0 = a[base], e1 = a[base + j], e2 = a[base + 2 * j], e3 = a[base + 3 * j];
    bool dir = ((base & k) == 0);
    cas64(e0, e2, dir); cas64(e1, e3, dir);
    cas64(e0, e1, dir); cas64(e2, e3, dir);
    a[base] = e0; a[base + j] = e1; a[base + 2 * j] = e2; a[base + 3 * j] = e3;
}

__device__ __forceinline__ void single128(u64* a, int k, int tid) {
#pragma unroll
    for (int rep = 0; rep < 2; rep++) {
        int p = tid + rep * 512;
        int i = ((p >> 7) << 8) | (p & 127);
        u64 x = a[i], y = a[i + 128];
        bool dir = ((i & k) == 0);
        bool sw = dir ? (x < y) : (x > y);
        if (sw) { a[i] = y; a[i + 128] = x; }
    }
}

__global__ __launch_bounds__(NT, 1)
void aps_kernel(const float* __restrict__ score_pred,
                const float* __restrict__ map2d,
                const float* __restrict__ offset_gt,
                const float* __restrict__ tmap,
                float* __restrict__ out) {
    extern __shared__ char smem[];
    u64*  fkey  = (u64*)(smem + OFF_FKEY);
    u64*  mkey  = (u64*)(smem + OFF_MKEY);
    u64*  extra = (u64*)(smem + OFF_EXTRA);
    unsigned*       mom  = (unsigned*)      (smem + OFF_MOM);
    unsigned char*  rr   = (unsigned char*) (smem + OFF_RR);
    unsigned char*  cc   = (unsigned char*) (smem + OFF_CC);
    unsigned short* unsupIdx = (unsigned short*)(smem + OFF_UNSUP);
    unsigned short* selIdx   = (unsigned short*)(smem + OFF_SELIDX);
    int* wsum = (int*)(smem + OFF_WSUM);      // [0..16] unsup excl, [17] tot, [20..36] sel excl, [37] tot
    int* fr   = (int*)(smem + OFF_FR);
    int* fc   = (int*)(smem + OFF_FC);
    unsigned* supw = (unsigned*)(smem + OFF_SUPW);
    unsigned* selw = (unsigned*)(smem + OFF_SELW);

    const int b    = blockIdx.x;
    const int tid  = threadIdx.x;
    const int lane = tid & 31, wid = tid >> 5;
    const bool sorter = (wid < 16);
    const unsigned lm_le = 0xffffffffu >> (31 - lane);

    // --- 1. (r,c) tables ---
    if (tid < NN) {
        int r = tid;
        int base = r * NN - (r * (r - 1)) / 2;
        for (int c = r; c < NN; c++) {
            int p = base + (c - r);
            rr[p] = (unsigned char)r;
            cc[p] = (unsigned char)c;
        }
    }
    __syncthreads();

    // --- 2. build keys: (orderable_f32 << 32) | (2079 - p) ---
    u64 e[4];
    if (sorter) {
#pragma unroll
        for (int v = 0; v < 4; v++) {
            int p = tid * 4 + v;
            int r = rr[p], c = cc[p];
            float s = score_pred[((size_t)b * NN + r) * NN + c];
            unsigned ub = __float_as_uint(s);
            ub = (ub & 0x80000000u) ? ~ub : (ub | 0x80000000u);
            e[v] = ((u64)ub << 32) | (unsigned)(2079 - p);
        }
        reg_stages<1 >(e, tid, lane, 2);
        reg_stages<2 >(e, tid, lane, 4);
        reg_stages<4 >(e, tid, lane, 8);
        reg_stages<8 >(e, tid, lane, 16);
        reg_stages<16>(e, tid, lane, 32);
        reg_stages<32>(e, tid, lane, 64);
        reg_stages<64>(e, tid, lane, 128);
    } else {   // wid == 16: sort the 32 extras with shuffles
        int p = MAIN + lane;
        int r = rr[p], c = cc[p];
        float s = score_pred[((size_t)b * NN + r) * NN + c];
        unsigned ub = __float_as_uint(s);
        ub = (ub & 0x80000000u) ? ~ub : (ub | 0x80000000u);
        u64 x = ((u64)ub << 32) | (unsigned)(2079 - p);
#pragma unroll
        for (int k2 = 2; k2 <= 32; k2 <<= 1) {
            bool dirk = ((lane & k2) == 0);
#pragma unroll
            for (int j2 = 16; j2 >= 1; j2 >>= 1) {
                if (j2 < k2) {
                    u64 pr = __shfl_xor_sync(0xffffffffu, x, j2);
                    bool keepMax = (((lane & j2) == 0) == dirk);
                    u64 mx = x > pr ? x : pr;
                    u64 mn = x > pr ? pr : x;
                    x = keepMax ? mx : mn;
                }
            }
        }
        extra[lane] = x;
    }

    // --- 3. merges k=256..2048 ---
#pragma unroll 1
    for (int k = 256; k <= MAIN; k <<= 1) {
        if (sorter) {
#pragma unroll
            for (int v = 0; v < 4; v++) mkey[tid * 4 + v] = e[v];
        }
        __syncthreads();
        if (k == 256) {
            if (sorter) single128(mkey, k, tid);
        } else if (k == 512) {
            if (sorter) pass2(mkey, k, 128, 7, tid);
        } else if (k == 1024) {
            if (sorter) pass2(mkey, k, 256, 8, tid);
            __syncthreads();
            if (sorter) single128(mkey, k, tid);
        } else {
            if (sorter) pass2(mkey, k, 512, 9, tid);
            __syncthreads();
            if (sorter) pass2(mkey, k, 128, 7, tid);
        }
        __syncthreads();
        if (sorter) {
#pragma unroll
            for (int v = 0; v < 4; v++) e[v] = mkey[tid * 4 + v];
            reg_stages<64>(e, tid, lane, k);
        }
    }

    // --- 3d. publish + rank merge with extras; fused mom build ---
    if (sorter) {
#pragma unroll
        for (int v = 0; v < 4; v++) mkey[tid * 4 + v] = e[v];
    }
    __syncthreads();
    if (sorter) {
#pragma unroll
        for (int v = 0; v < 4; v++) {
            u64 x = e[v];
            int lo = 0, hiS = NEXTRA;
            while (lo < hiS) {
                int mid = (lo + hiS) >> 1;
                if (extra[mid] > x) lo = mid + 1; else hiS = mid;
            }
            int dst = tid * 4 + v + lo;
            fkey[dst] = x;
            int orig = 2079 - (int)(unsigned)(x & 0xFFFFFFFFull);
            mom[dst] = (unsigned)rr[orig] | (((unsigned)cc[orig] + 1u) << 16);
        }
    } else {
        u64 x = extra[lane];
        int lo = 0, hiS = MAIN;
        while (lo < hiS) {
            int mid = (lo + hiS) >> 1;
            if (mkey[mid] > x) lo = mid + 1; else hiS = mid;
        }
        int dst = lo + lane;
        fkey[dst] = x;
        int orig = 2079 - (int)(unsigned)(x & 0xFFFFFFFFull);
        mom[dst] = (unsigned)rr[orig] | (((unsigned)cc[orig] + 1u) << 16);
    }
    __syncthreads();

    // --- 5. NMS: single warp, all moments in registers, zero barriers ---
    if (wid == 0) {
        unsigned momv[65];
#pragma unroll
        for (int v = 0; v < 65; v++) momv[v] = mom[v * 32 + lane];

        unsigned sup0 = 0, sup1 = 0, sup2 = 0;   // bit v: j = v*32+lane suppressed
        unsigned sel0 = 0, sel1 = 0, sel2 = 0;
        int piv = 0;                              // first pivot is always index 0
#pragma unroll 1
        for (int iter = 0; iter < TOPK && piv >= 0; iter++) {
            unsigned mp = mom[piv];               // LDS broadcast
            int s_i = (int)(mp & 0xffffu), e_i = (int)(mp >> 16);
            int run = 0;
#pragma unroll
            for (int v = 0; v < 65; v++) {
                int j = v * 32 + lane;
                unsigned m = momv[v];
                int sj = (int)(m & 0xffffu), ej = (int)(m >> 16);
                int inter = min(ej, e_i) - max(sj, s_i);
                int uni   = max(ej, e_i) - min(sj, s_i);
                bool match = (2 * inter > uni) && (j > piv);
                unsigned bal = __ballot_sync(0xffffffffu, match);
                if (match) {
                    int rank = run + __popc(bal & lm_le);   // 1-based in j-order
                    if (v < 32)      sup0 |= (1u << v);
                    else if (v < 64) sup1 |= (1u << (v - 32));
                    else             sup2 |= 1u;
                    if (rank <= NEIGHBOR) {
                        if (v < 32)      sel0 |= (1u << v);
                        else if (v < 64) sel1 |= (1u << (v - 32));
                        else             sel2 |= 1u;
                    }
                }
                run += __popc(bal);
            }
            // pivot's own sup/sel bits
            {
                int pv = piv >> 5, pl = piv & 31;
                if (lane == pl) {
                    if (pv < 32)      { sup0 |= 1u << pv;        sel0 |= 1u << pv; }
                    else if (pv < 64) { sup1 |= 1u << (pv - 32); sel1 |= 1u << (pv - 32); }
                    else              { sup2 |= 1u;              sel2 |= 1u; }
                }
            }
            // next pivot: first j < MV-1 with sup bit clear
            if (iter < TOPK - 1) {
                int np = -1;
#pragma unroll
                for (int v = 0; v < 65; v++) {
                    if (np < 0) {
                        bool freeb;
                        if (v < 32)      freeb = ((sup0 >> v) & 1u) == 0u;
                        else if (v < 64) freeb = ((sup1 >> (v - 32)) & 1u) == 0u;
                        else             freeb = (sup2 & 1u) == 0u;
                        if (v == 64 && lane == 31) freeb = false;   // exclude j = 2079
                        unsigned w = __ballot_sync(0xffffffffu, freeb);
                        if (w) np = v * 32 + (__ffs(w) - 1);
                    }
                }
                piv = np;
            }
        }
        // publish sup/sel as 65-word bitmaps
#pragma unroll
        for (int v = 0; v < 65; v++) {
            bool sb = (v < 32) ? (((sup0 >> v) & 1u) != 0u)
                    : (v < 64) ? (((sup1 >> (v - 32)) & 1u) != 0u)
                               : ((sup2 & 1u) != 0u);
            bool eb = (v < 32) ? (((sel0 >> v) & 1u) != 0u)
                    : (v < 64) ? (((sel1 >> (v - 32)) & 1u) != 0u)
                               : ((sel2 & 1u) != 0u);
            unsigned ws = __ballot_sync(0xffffffffu, sb);
            unsigned we = __ballot_sync(0xffffffffu, eb);
            if (lane == 0) { supw[v] = ws; selw[v] = we; }
        }
    }
    __syncthreads();

    // --- 6. fused dual compaction from bitmap words (4 elems/thread, 520 threads) ---
    unsigned nibU = 0, nibS = 0;
    int lU = 0, lS = 0;
    if (tid < 520) {
        unsigned wsv = supw[tid >> 3];
        unsigned wev = selw[tid >> 3];
        int sh = (tid & 7) * 4;
        unsigned su = (wsv >> sh) & 0xFu;
        nibU = (~su) & 0xFu;                 // unsuppressed
        nibS = (wev >> sh) & 0xFu;           // selected
        lU = __popc(nibU); lS = __popc(nibS);
    }
    int xU = lU, xS = lS;
#pragma unroll
    for (int d = 1; d < 32; d <<= 1) {
        int yU = __shfl_up_sync(0xffffffffu, xU, d);
        int yS = __shfl_up_sync(0xffffffffu, xS, d);
        if (lane >= d) { xU += yU; xS += yS; }
    }
    if (lane == 31) { wsum[wid] = xU; wsum[20 + wid] = xS; }
    __syncthreads();
    if (wid == 0) {
        int vU = (lane < 17) ? wsum[lane] : 0;
        int vS = (lane < 17) ? wsum[20 + lane] : 0;
        int xxU = vU, xxS = vS;
#pragma unroll
        for (int d = 1; d < 32; d <<= 1) {
            int yU = __shfl_up_sync(0xffffffffu, xxU, d);
            int yS = __shfl_up_sync(0xffffffffu, xxS, d);
            if (lane >= d) { xxU += yU; xxS += yS; }
        }
        if (lane < 17) { wsum[lane] = xxU - vU; wsum[20 + lane] = xxS - vS; }
        if (lane == 16) { wsum[17] = xxU; wsum[37] = xxS; }
    }
    __syncthreads();
    if (tid < 520) {
        int baseU = wsum[wid] + xU - lU;
        int baseS = wsum[20 + wid] + xS - lS;
#pragma unroll
        for (int u = 0; u < 4; u++) {
            int j = 4 * tid + u;
            if ((nibU >> u) & 1u) unsupIdx[baseU++] = (unsigned short)j;
            if ((nibS >> u) & 1u) selIdx[baseS++]   = (unsigned short)j;
        }
    }
    int nUnsup = wsum[17];
    int nSel   = wsum[37];
    __syncthreads();

    // --- 7. final index assembly + small outputs ---
    float* feat = out;
    float* se   = out + (size_t)NB * KOUT * DFEAT;
    float* off  = se  + (size_t)NB * KOUT * 2;
    float* sc   = off + (size_t)NB * KOUT * 2;

    if (tid < KOUT) {
        int k = tid;
        int val;
        if (k < NEGATIVE) {
            int pos = nUnsup - 1 - k;
            if (pos < 0) pos = 0;
            val = (pos < nUnsup) ? (int)unsupIdx[pos] : (MV - 1);
        } else {
            int p = k - NEGATIVE;
            int pad = TOTAL - nSel;
            if (p < pad) {
                val = (p < nUnsup) ? (int)unsupIdx[p] : (MV - 1);
            } else {
                val = (int)selIdx[p - pad];
            }
        }
        int orig = 2079 - (int)(unsigned)(fkey[val] & 0xFFFFFFFFull);
        int r = rr[orig], c = cc[orig];
        fr[k] = r; fc[k] = c;

        size_t o = (size_t)b * KOUT + k;
        se[o * 2 + 0] = (float)r;
        se[o * 2 + 1] = (float)(c + 1);
        size_t cell = ((size_t)b * NN + r) * NN + c;
        off[o * 2 + 0] = offset_gt[cell * 2 + 0];
        off[o * 2 + 1] = offset_gt[cell * 2 + 1];
        sc[o] = tmap[cell];
    }
    __syncthreads();

    // --- 8. feature gather (float4) ---
    const float4* src = (const float4*)map2d;
    float4* dst = (float4*)feat;
    const int VEC = DFEAT / 4;   // 128
    for (int t = tid; t < KOUT * VEC; t += NT) {
        int k = t >> 7;
        int d = t & (VEC - 1);
        int r = fr[k], c = fc[k];
        dst[((size_t)b * KOUT + k) * VEC + d] =
            src[(((size_t)b * NN + r) * NN + c) * VEC + d];
    }
}

extern "C" void kernel_launch(void* const* d_in, const int* in_sizes, int n_in,
                              void* d_out, int out_size) {
    const float* score_pred = (const float*)d_in[0];
    // d_in[1] = map2d_mask (deterministic triu(ones)) — computed analytically
    const float* map2d      = (const float*)d_in[2];
    const float* offset_gt  = (const float*)d_in[3];
    const float* tmap       = (const float*)d_in[4];
    float* out = (float*)d_out;

    cudaFuncSetAttribute(aps_kernel, cudaFuncAttributeMaxDynamicSharedMemorySize,
                         SMEM_BYTES);
    aps_kernel<<<NB, NT, SMEM_BYTES>>>(score_pred, map2d, offset_gt, tmap, out);
}

// round 13
// speedup vs baseline: 2.0522x; 2.0522x over previous
#include <cuda_runtime.h>
#include <cuda_bf16.h>
#include <stdint.h>

// Problem constants
#define NB      32
#define NN      64
#define MV      2080          // NN*(NN+1)/2
#define MAIN    2048
#define NEXTRA  32
#define TOPK    5
#define NEIGHBOR 16
#define NEGATIVE 16
#define TOTAL   85            // TOPK*(NEIGHBOR+1)
#define KOUT    101           // NEGATIVE + TOTAL
#define DFEAT   512
#define NT      1024

// dynamic smem layout (byte offsets)
#define OFF_FKEY    0          // u64[2080]  16640
#define OFF_MKEY    16640      // u64[2048]  16384
#define OFF_EXTRA   33024      // u64[32]      256
#define OFF_MOM     33280      // u32[2080]   8320
#define OFF_RR      41600      // u8[2080]
#define OFF_CC      43680      // u8[2080]
#define OFF_SUP     45760      // u8[2080]
#define OFF_SEL     47840      // u8[2080]
#define OFF_UNSUP   49920      // u16[2080]   4160
#define OFF_SELIDX  54080      // u16[96]      192
#define OFF_WSUM    54272      // int[68]      272
#define OFF_FR      54544      // int[101]     404
#define OFF_FC      54948      // int[101]     404
#define OFF_WORDS   55352      // u32[65]      260
#define OFF_PFX     55612      // int[66]      264
#define OFF_PIV     55876      // int[4]        16
#define SMEM_BYTES  55936

#define BARS() asm volatile("bar.sync 1, 512;" ::: "memory")

typedef unsigned long long u64;

__device__ __forceinline__ void cas64(u64& a, u64& b, bool dir) {
    u64 x = a, y = b;
    bool sw = dir ? (x < y) : (x > y);
    a = sw ? y : x;
    b = sw ? x : y;
}

template<int J0>
__device__ __forceinline__ void reg_stages(u64 e[4], int tid, int lane, int k) {
    const int base = tid * 4;
    const bool dirU = ((base & k) == 0);
#pragma unroll
    for (int j = J0; j >= 4; j >>= 1) {
        int lm = j >> 2;
        bool lower = ((lane & lm) == 0);
        bool keepMax = (lower == dirU);
#pragma unroll
        for (int v = 0; v < 4; v++) {
            u64 p = __shfl_xor_sync(0xffffffffu, e[v], lm);
            u64 mx = e[v] > p ? e[v] : p;
            u64 mn = e[v] > p ? p : e[v];
            e[v] = keepMax ? mx : mn;
        }
    }
    if (J0 >= 2) {
        cas64(e[0], e[2], dirU);
        cas64(e[1], e[3], dirU);
    }
    if (k == 2) {
        cas64(e[0], e[1], true);
        cas64(e[2], e[3], false);
    } else {
        cas64(e[0], e[1], dirU);
        cas64(e[2], e[3], dirU);
    }
}

// Two levels (2j, j) of merge k over 2048 elems; 512 sorter threads.
__device__ __forceinline__ void pass2(u64* a, int k, int j, int lg, int tid) {
    int low  = tid & (j - 1);
    int hi   = tid >> lg;
    int base = (hi << (lg + 2)) | low;
    u64 e0 = a[base], e1 = a[base + j], e2 = a[base + 2 * j], e3 = a[base + 3 * j];
    bool dir = ((base & k) == 0);
    cas64(e0, e2, dir); cas64(e1, e3, dir);
    cas64(e0, e1, dir); cas64(e2, e3, dir);
    a[base] = e0; a[base + j] = e1; a[base + 2 * j] = e2; a[base + 3 * j] = e3;
}

__device__ __forceinline__ void single128(u64* a, int k, int tid) {
#pragma unroll
    for (int rep = 0; rep < 2; rep++) {
        int p = tid + rep * 512;
        int i = ((p >> 7) << 8) | (p & 127);
        u64 x = a[i], y = a[i + 128];
        bool dir = ((i & k) == 0);
        bool sw = dir ? (x < y) : (x > y);
        if (sw) { a[i] = y; a[i + 128] = x; }
    }
}

__global__ __launch_bounds__(NT, 1)
void aps_kernel(const float* __restrict__ score_pred,
                const float* __restrict__ map2d,
                const float* __restrict__ offset_gt,
                const float* __restrict__ tmap,
                float* __restrict__ out) {
    extern __shared__ char smem[];
    u64*  fkey  = (u64*)(smem + OFF_FKEY);
    u64*  mkey  = (u64*)(smem + OFF_MKEY);
    u64*  extra = (u64*)(smem + OFF_EXTRA);
    unsigned*       mom  = (unsigned*)      (smem + OFF_MOM);
    unsigned char*  rr   = (unsigned char*) (smem + OFF_RR);
    unsigned char*  cc   = (unsigned char*) (smem + OFF_CC);
    unsigned char*  sup  = (unsigned char*) (smem + OFF_SUP);
    unsigned char*  sel  = (unsigned char*) (smem + OFF_SEL);
    unsigned short* unsupIdx = (unsigned short*)(smem + OFF_UNSUP);
    unsigned short* selIdx   = (unsigned short*)(smem + OFF_SELIDX);
    int* wsum = (int*)(smem + OFF_WSUM);       // [0..32] unsup, [34..66] sel
    int* fr   = (int*)(smem + OFF_FR);
    int* fc   = (int*)(smem + OFF_FC);
    unsigned* words = (unsigned*)(smem + OFF_WORDS);
    int* pfx  = (int*)(smem + OFF_PFX);
    int* pivinfo = (int*)(smem + OFF_PIV);

    const int b    = blockIdx.x;
    const int tid  = threadIdx.x;
    const int lane = tid & 31, wid = tid >> 5;
    const bool sorter = (wid < 16);
    const unsigned lm_le = 0xffffffffu >> (31 - lane);   // lanes <= me

    // --- 1. (r,c) tables ---
    if (tid < NN) {
        int r = tid;
        int base = r * NN - (r * (r - 1)) / 2;
        for (int c = r; c < NN; c++) {
            int p = base + (c - r);
            rr[p] = (unsigned char)r;
            cc[p] = (unsigned char)c;
        }
    }
    __syncthreads();

    // --- 2. build keys in registers + clear bitmaps ---
    u64 e[4];
    if (sorter) {
#pragma unroll
        for (int v = 0; v < 4; v++) {
            int p = tid * 4 + v;
            int r = rr[p], c = cc[p];
            float s = score_pred[((size_t)b * NN + r) * NN + c];
            unsigned ub = __float_as_uint(s);
            ub = (ub & 0x80000000u) ? ~ub : (ub | 0x80000000u);
            e[v] = ((u64)ub << 32) | (unsigned)(2079 - p);
        }
    } else if (wid == 16) {
        int p = MAIN + lane;
        int r = rr[p], c = cc[p];
        float s = score_pred[((size_t)b * NN + r) * NN + c];
        unsigned ub = __float_as_uint(s);
        ub = (ub & 0x80000000u) ? ~ub : (ub | 0x80000000u);
        u64 x = ((u64)ub << 32) | (unsigned)(2079 - p);
#pragma unroll
        for (int k2 = 2; k2 <= 32; k2 <<= 1) {
            bool dirk = ((lane & k2) == 0);
#pragma unroll
            for (int j2 = 16; j2 >= 1; j2 >>= 1) {
                if (j2 < k2) {
                    u64 pr = __shfl_xor_sync(0xffffffffu, x, j2);
                    bool keepMax = (((lane & j2) == 0) == dirk);
                    u64 mx = x > pr ? x : pr;
                    u64 mn = x > pr ? pr : x;
                    x = keepMax ? mx : mn;
                }
            }
        }
        extra[lane] = x;
    }
    // clear sup/sel (touched only by NMS, much later)
    sup[tid] = 0; sel[tid] = 0;
    sup[tid + 1024] = 0; sel[tid + 1024] = 0;
    if (tid < 32) { sup[2048 + tid] = 0; sel[2048 + tid] = 0; }

    // --- 3. sort on 16 warps; sorter-only named barriers ---
    if (sorter) {
        reg_stages<1 >(e, tid, lane, 2);
        reg_stages<2 >(e, tid, lane, 4);
        reg_stages<4 >(e, tid, lane, 8);
        reg_stages<8 >(e, tid, lane, 16);
        reg_stages<16>(e, tid, lane, 32);
        reg_stages<32>(e, tid, lane, 64);
        reg_stages<64>(e, tid, lane, 128);

#pragma unroll 1
        for (int k = 256; k <= MAIN; k <<= 1) {
#pragma unroll
            for (int v = 0; v < 4; v++) mkey[tid * 4 + v] = e[v];
            BARS();
            if (k == 256) {
                single128(mkey, k, tid);
            } else if (k == 512) {
                pass2(mkey, k, 128, 7, tid);
            } else if (k == 1024) {
                pass2(mkey, k, 256, 8, tid);
                BARS();
                single128(mkey, k, tid);
            } else {
                pass2(mkey, k, 512, 9, tid);
                BARS();
                pass2(mkey, k, 128, 7, tid);
            }
            BARS();
#pragma unroll
            for (int v = 0; v < 4; v++) e[v] = mkey[tid * 4 + v];
            reg_stages<64>(e, tid, lane, k);
        }
        // publish sorted main run
#pragma unroll
        for (int v = 0; v < 4; v++) mkey[tid * 4 + v] = e[v];
    }
    __syncthreads();   // full: mkey + extra visible to everyone

    // --- 3d. rank merge with extras; fused mom build ---
    if (sorter) {
#pragma unroll
        for (int v = 0; v < 4; v++) {
            u64 x = e[v];
            int lo = 0, hiS = NEXTRA;
            while (lo < hiS) {
                int mid = (lo + hiS) >> 1;
                if (extra[mid] > x) lo = mid + 1; else hiS = mid;
            }
            int dst = tid * 4 + v + lo;
            fkey[dst] = x;
            int orig = 2079 - (int)(unsigned)(x & 0xFFFFFFFFull);
            mom[dst] = (unsigned)rr[orig] | (((unsigned)cc[orig] + 1u) << 16);
        }
    } else if (wid == 16) {
        u64 x = extra[lane];
        int lo = 0, hiS = MAIN;
        while (lo < hiS) {
            int mid = (lo + hiS) >> 1;
            if (mkey[mid] > x) lo = mid + 1; else hiS = mid;
        }
        int dst = lo + lane;
        fkey[dst] = x;
        int orig = 2079 - (int)(unsigned)(x & 0xFFFFFFFFull);
        mom[dst] = (unsigned)rr[orig] | (((unsigned)cc[orig] + 1u) << 16);
    }
    __syncthreads();

    // --- 4. cache moments in registers (no extra barrier) ---
    unsigned momA = mom[tid];
    unsigned momB = mom[tid + 1024];
    unsigned momC = (wid == 0) ? mom[2048 + tid] : 0u;

    // --- 5. NMS: 2 barriers per pivot, register suppressed-bitmap in warp 0 ---
    unsigned cumA = 0, cumB = 0, cumC = 0;   // warp 0 only
    bool m1p = false, m2p = false, m3p = false;
    int  r1p = 0, r2p = 0, r3p = 0;
    int  piv = 0;                             // first pivot is always index 0
#pragma unroll 1
    for (int iter = 0; iter <= TOPK; iter++) {
        if (iter > 0) piv = pivinfo[0];
        // deferred writes for previous pivot
        if (m1p) { int rank = pfx[wid] + r1p;      sup[tid] = 1;        if (rank <= NEIGHBOR) sel[tid] = 1; }
        if (m2p) { int rank = pfx[32 + wid] + r2p; sup[tid + 1024] = 1; if (rank <= NEIGHBOR) sel[tid + 1024] = 1; }
        if (m3p) { int rank = pfx[64] + r3p;       sup[2048 + tid] = 1; if (rank <= NEIGHBOR) sel[2048 + tid] = 1; }
        if (iter == TOPK || piv < 0) break;

        unsigned mp = mom[piv];    // LDS broadcast (mom stable after 3d)
        int s_i = (int)(mp & 0xffffu), e_i = (int)(mp >> 16);

        // phase A: matches from cached moments
        {
            int sj = (int)(momA & 0xffffu), ej = (int)(momA >> 16);
            int inter = min(ej, e_i) - max(sj, s_i);
            int uni   = max(ej, e_i) - min(sj, s_i);
            m1p = (2 * inter > uni) && (tid > piv);
        }
        {
            int sj = (int)(momB & 0xffffu), ej = (int)(momB >> 16);
            int inter = min(ej, e_i) - max(sj, s_i);
            int uni   = max(ej, e_i) - min(sj, s_i);
            m2p = (2 * inter > uni) && (tid + 1024 > piv);
        }
        unsigned b1 = __ballot_sync(0xffffffffu, m1p);
        unsigned b2 = __ballot_sync(0xffffffffu, m2p);
        r1p = __popc(b1 & lm_le);
        r2p = __popc(b2 & lm_le);
        if (lane == 0) { words[wid] = b1; words[32 + wid] = b2; }
        if (wid == 0) {
            int sj = (int)(momC & 0xffffu), ej = (int)(momC >> 16);
            int inter = min(ej, e_i) - max(sj, s_i);
            int uni   = max(ej, e_i) - min(sj, s_i);
            m3p = (2 * inter > uni) && (2048 + tid > piv);
            unsigned b3 = __ballot_sync(0xffffffffu, m3p);
            r3p = __popc(b3 & lm_le);
            if (lane == 0) words[64] = b3;
        } else { m3p = false; }
        __syncthreads();

        // phase B: warp 0 — prefix, cum bitmap, pivot sup/sel, next pivot
        if (wid == 0) {
            unsigned w0 = words[lane], w1 = words[32 + lane], wX = words[64];
            int c0 = __popc(w0), x0 = c0;
#pragma unroll
            for (int d = 1; d < 32; d <<= 1) {
                int y = __shfl_up_sync(0xffffffffu, x0, d);
                if (lane >= d) x0 += y;
            }
            pfx[lane] = x0 - c0;
            int tot0 = __shfl_sync(0xffffffffu, x0, 31);
            int c1 = __popc(w1), x1 = c1;
#pragma unroll
            for (int d = 1; d < 32; d <<= 1) {
                int y = __shfl_up_sync(0xffffffffu, x1, d);
                if (lane >= d) x1 += y;
            }
            pfx[32 + lane] = tot0 + x1 - c1;
            if (lane == 31) pfx[64] = tot0 + x1;

            cumA |= w0; cumB |= w1;
            if (lane == 0) cumC |= wX;
            int pw = piv >> 5, pb = piv & 31;
            if (pw < 32)      { if (lane == pw)      cumA |= (1u << pb); }
            else if (pw < 64) { if (lane == pw - 32) cumB |= (1u << pb); }
            else              { if (lane == 0)       cumC |= (1u << pb); }
            if (lane == 0) { sup[piv] = 1; sel[piv] = 1; }

            // next pivot = first free index < MV-1
            unsigned fA = ~cumA;
            unsigned balA = __ballot_sync(0xffffffffu, fA != 0u);
            int npiv = -1;
            if (balA) {
                int l0 = __ffs(balA) - 1;
                unsigned f = __shfl_sync(0xffffffffu, fA, l0);
                npiv = l0 * 32 + __ffs(f) - 1;
            } else {
                unsigned fB = ~cumB;
                unsigned balB = __ballot_sync(0xffffffffu, fB != 0u);
                if (balB) {
                    int l0 = __ffs(balB) - 1;
                    unsigned f = __shfl_sync(0xffffffffu, fB, l0);
                    npiv = (32 + l0) * 32 + __ffs(f) - 1;
                } else {
                    unsigned fC = (~cumC) & 0x7fffffffu;   // exclude j = 2079
                    fC = __shfl_sync(0xffffffffu, fC, 0);
                    if (fC) npiv = 2048 + __ffs(fC) - 1;
                }
            }
            if (lane == 0) pivinfo[0] = npiv;
        }
        __syncthreads();
    }
    __syncthreads();

    // --- 6. fused dual compaction ( !sup -> unsupIdx , sel -> selIdx ) ---
    bool pU[3], pS[3]; int lU = 0, lS = 0;
#pragma unroll
    for (int u = 0; u < 3; u++) {
        int j = 3 * tid + u;
        bool valid = (j < MV);
        unsigned char sv = valid ? sup[j] : 1;
        unsigned char ev = valid ? sel[j] : 0;
        pU[u] = valid && (sv == 0);
        pS[u] = valid && (ev != 0);
        lU += (int)pU[u]; lS += (int)pS[u];
    }
    int xU = lU, xS = lS;
#pragma unroll
    for (int d = 1; d < 32; d <<= 1) {
        int yU = __shfl_up_sync(0xffffffffu, xU, d);
        int yS = __shfl_up_sync(0xffffffffu, xS, d);
        if (lane >= d) { xU += yU; xS += yS; }
    }
    if (lane == 31) { wsum[wid] = xU; wsum[34 + wid] = xS; }
    __syncthreads();
    if (wid == 0) {
        int vU = wsum[lane], vS = wsum[34 + lane];
        int xxU = vU, xxS = vS;
#pragma unroll
        for (int d = 1; d < 32; d <<= 1) {
            int yU = __shfl_up_sync(0xffffffffu, xxU, d);
            int yS = __shfl_up_sync(0xffffffffu, xxS, d);
            if (lane >= d) { xxU += yU; xxS += yS; }
        }
        wsum[lane] = xxU - vU;
        wsum[34 + lane] = xxS - vS;
        if (lane == 31) { wsum[32] = xxU; wsum[66] = xxS; }
    }
    __syncthreads();
    {
        int baseU = wsum[wid] + xU - lU;
        int baseS = wsum[34 + wid] + xS - lS;
#pragma unroll
        for (int u = 0; u < 3; u++) {
            if (pU[u]) unsupIdx[baseU++] = (unsigned short)(3 * tid + u);
            if (pS[u]) selIdx[baseS++]   = (unsigned short)(3 * tid + u);
        }
    }
    int nUnsup = wsum[32];
    int nSel   = wsum[66];
    __syncthreads();

    // --- 7. final index assembly + small outputs ---
    float* feat = out;
    float* se   = out + (size_t)NB * KOUT * DFEAT;
    float* off  = se  + (size_t)NB * KOUT * 2;
    float* sc   = off + (size_t)NB * KOUT * 2;

    if (tid < KOUT) {
        int k = tid;
        int val;
        if (k < NEGATIVE) {
            int pos = nUnsup - 1 - k;
            if (pos < 0) pos = 0;
            val = (pos < nUnsup) ? (int)unsupIdx[pos] : (MV - 1);
        } else {
            int p = k - NEGATIVE;
            int pad = TOTAL - nSel;
            if (p < pad) {
                val = (p < nUnsup) ? (int)unsupIdx[p] : (MV - 1);
            } else {
                val = (int)selIdx[p - pad];
            }
        }
        int orig = 2079 - (int)(unsigned)(fkey[val] & 0xFFFFFFFFull);
        int r = rr[orig], c = cc[orig];
        fr[k] = r; fc[k] = c;

        size_t o = (size_t)b * KOUT + k;
        se[o * 2 + 0] = (float)r;
        se[o * 2 + 1] = (float)(c + 1);
        size_t cell = ((size_t)b * NN + r) * NN + c;
        off[o * 2 + 0] = offset_gt[cell * 2 + 0];
        off[o * 2 + 1] = offset_gt[cell * 2 + 1];
        sc[o] = tmap[cell];
    }
    __syncthreads();

    // --- 8. feature gather (float4) ---
    const float4* src = (const float4*)map2d;
    float4* dst = (float4*)feat;
    const int VEC = DFEAT / 4;   // 128
    for (int t = tid; t < KOUT * VEC; t += NT) {
        int k = t >> 7;
        int d = t & (VEC - 1);
        int r = fr[k], c = fc[k];
        dst[((size_t)b * KOUT + k) * VEC + d] =
            src[(((size_t)b * NN + r) * NN + c) * VEC + d];
    }
}

extern "C" void kernel_launch(void* const* d_in, const int* in_sizes, int n_in,
                              void* d_out, int out_size) {
    const float* score_pred = (const float*)d_in[0];
    // d_in[1] = map2d_mask (deterministic triu(ones)) — computed analytically
    const float* map2d      = (const float*)d_in[2];
    const float* offset_gt  = (const float*)d_in[3];
    const float* tmap       = (const float*)d_in[4];
    float* out = (float*)d_out;

    cudaFuncSetAttribute(aps_kernel, cudaFuncAttributeMaxDynamicSharedMemorySize,
                         SMEM_BYTES);
    aps_kernel<<<NB, NT, SMEM_BYTES>>>(score_pred, map2d, offset_gt, tmap, out);
}

// round 14
// speedup vs baseline: 2.0575x; 1.0026x over previous
#include <cuda_runtime.h>
#include <cuda_bf16.h>
#include <stdint.h>

// Problem constants
#define NB      32
#define NN      64
#define MV      2080          // NN*(NN+1)/2
#define MAIN    2048
#define NEXTRA  32
#define TOPK    5
#define NEIGHBOR 16
#define NEGATIVE 16
#define TOTAL   85            // TOPK*(NEIGHBOR+1)
#define KOUT    101           // NEGATIVE + TOTAL
#define DFEAT   512
#define NT      1024

// dynamic smem layout (byte offsets)
#define OFF_FKEY    0          // u64[2080]  16640
#define OFF_MKEY    16640      // u64[2048]  16384
#define OFF_EXTRA   33024      // u64[32]      256
#define OFF_MOM     33280      // u32[2080]   8320
#define OFF_RR      41600      // u8[2080]
#define OFF_CC      43680      // u8[2080]
#define OFF_SUP     45760      // u8[2080]
#define OFF_SEL     47840      // u8[2080]
#define OFF_UNSUP   49920      // u16[2080]   4160
#define OFF_SELIDX  54080      // u16[96]      192
#define OFF_WSUM    54272      // u32[32]      128 (packed U|S<<16)
#define OFF_FR      54400      // int[101]     404
#define OFF_FC      54804      // int[101]     404
#define OFF_WORDS0  55208      // u32[65]      260
#define OFF_WORDS1  55468      // u32[65]      260
#define SMEM_BYTES  55808

#define BARS() asm volatile("bar.sync 1, 512;" ::: "memory")

typedef unsigned long long u64;

__device__ __forceinline__ void cas64(u64& a, u64& b, bool dir) {
    u64 x = a, y = b;
    bool sw = dir ? (x < y) : (x > y);
    a = sw ? y : x;
    b = sw ? x : y;
}

template<int J0>
__device__ __forceinline__ void reg_stages(u64 e[4], int tid, int lane, int k) {
    const int base = tid * 4;
    const bool dirU = ((base & k) == 0);
#pragma unroll
    for (int j = J0; j >= 4; j >>= 1) {
        int lm = j >> 2;
        bool lower = ((lane & lm) == 0);
        bool keepMax = (lower == dirU);
#pragma unroll
        for (int v = 0; v < 4; v++) {
            u64 p = __shfl_xor_sync(0xffffffffu, e[v], lm);
            u64 mx = e[v] > p ? e[v] : p;
            u64 mn = e[v] > p ? p : e[v];
            e[v] = keepMax ? mx : mn;
        }
    }
    if (J0 >= 2) {
        cas64(e[0], e[2], dirU);
        cas64(e[1], e[3], dirU);
    }
    if (k == 2) {
        cas64(e[0], e[1], true);
        cas64(e[2], e[3], false);
    } else {
        cas64(e[0], e[1], dirU);
        cas64(e[2], e[3], dirU);
    }
}

// Two levels (2j, j) of merge k over 2048 elems; 512 sorter threads.
__device__ __forceinline__ void pass2(u64* a, int k, int j, int lg, int tid) {
    int low  = tid & (j - 1);
    int hi   = tid >> lg;
    int base = (hi << (lg + 2)) | low;
    u64 e0 = a[base], e1 = a[base + j], e2 = a[base + 2 * j], e3 = a[base + 3 * j];
    bool dir = ((base & k) == 0);
    cas64(e0, e2, dir); cas64(e1, e3, dir);
    cas64(e0, e1, dir); cas64(e2, e3, dir);
    a[base] = e0; a[base + j] = e1; a[base + 2 * j] = e2; a[base + 3 * j] = e3;
}

__device__ __forceinline__ void single128(u64* a, int k, int tid) {
#pragma unroll
    for (int rep = 0; rep < 2; rep++) {
        int p = tid + rep * 512;
        int i = ((p >> 7) << 8) | (p & 127);
        u64 x = a[i], y = a[i + 128];
        bool dir = ((i & k) == 0);
        bool sw = dir ? (x < y) : (x > y);
        if (sw) { a[i] = y; a[i + 128] = x; }
    }
}

__device__ __forceinline__ unsigned bfly_sum(unsigned x) {
#pragma unroll
    for (int d = 16; d >= 1; d >>= 1) x += __shfl_xor_sync(0xffffffffu, x, d);
    return x;
}

__global__ __launch_bounds__(NT, 1)
void aps_kernel(const float* __restrict__ score_pred,
                const float* __restrict__ map2d,
                const float* __restrict__ offset_gt,
                const float* __restrict__ tmap,
                float* __restrict__ out) {
    extern __shared__ char smem[];
    u64*  fkey  = (u64*)(smem + OFF_FKEY);
    u64*  mkey  = (u64*)(smem + OFF_MKEY);
    u64*  extra = (u64*)(smem + OFF_EXTRA);
    unsigned*       mom  = (unsigned*)      (smem + OFF_MOM);
    unsigned char*  rr   = (unsigned char*) (smem + OFF_RR);
    unsigned char*  cc   = (unsigned char*) (smem + OFF_CC);
    unsigned char*  sup  = (unsigned char*) (smem + OFF_SUP);
    unsigned char*  sel  = (unsigned char*) (smem + OFF_SEL);
    unsigned short* unsupIdx = (unsigned short*)(smem + OFF_UNSUP);
    unsigned short* selIdx   = (unsigned short*)(smem + OFF_SELIDX);
    unsigned* wsum = (unsigned*)(smem + OFF_WSUM);
    int* fr   = (int*)(smem + OFF_FR);
    int* fc   = (int*)(smem + OFF_FC);
    unsigned* words0 = (unsigned*)(smem + OFF_WORDS0);
    unsigned* words1 = (unsigned*)(smem + OFF_WORDS1);

    const int b    = blockIdx.x;
    const int tid  = threadIdx.x;
    const int lane = tid & 31, wid = tid >> 5;
    const bool sorter = (wid < 16);
    const unsigned lm_le = 0xffffffffu >> (31 - lane);   // lanes <= me

    // --- 1. (r,c) tables ---
    if (tid < NN) {
        int r = tid;
        int base = r * NN - (r * (r - 1)) / 2;
        for (int c = r; c < NN; c++) {
            int p = base + (c - r);
            rr[p] = (unsigned char)r;
            cc[p] = (unsigned char)c;
        }
    }
    __syncthreads();

    // --- 2. build keys in registers + clear bitmaps ---
    u64 e[4];
    if (sorter) {
#pragma unroll
        for (int v = 0; v < 4; v++) {
            int p = tid * 4 + v;
            int r = rr[p], c = cc[p];
            float s = score_pred[((size_t)b * NN + r) * NN + c];
            unsigned ub = __float_as_uint(s);
            ub = (ub & 0x80000000u) ? ~ub : (ub | 0x80000000u);
            e[v] = ((u64)ub << 32) | (unsigned)(2079 - p);
        }
    } else if (wid == 16) {
        int p = MAIN + lane;
        int r = rr[p], c = cc[p];
        float s = score_pred[((size_t)b * NN + r) * NN + c];
        unsigned ub = __float_as_uint(s);
        ub = (ub & 0x80000000u) ? ~ub : (ub | 0x80000000u);
        u64 x = ((u64)ub << 32) | (unsigned)(2079 - p);
#pragma unroll
        for (int k2 = 2; k2 <= 32; k2 <<= 1) {
            bool dirk = ((lane & k2) == 0);
#pragma unroll
            for (int j2 = 16; j2 >= 1; j2 >>= 1) {
                if (j2 < k2) {
                    u64 pr = __shfl_xor_sync(0xffffffffu, x, j2);
                    bool keepMax = (((lane & j2) == 0) == dirk);
                    u64 mx = x > pr ? x : pr;
                    u64 mn = x > pr ? pr : x;
                    x = keepMax ? mx : mn;
                }
            }
        }
        extra[lane] = x;
    }
    // clear sup/sel (touched only by NMS, much later)
    sup[tid] = 0; sel[tid] = 0;
    sup[tid + 1024] = 0; sel[tid + 1024] = 0;
    if (tid < 32) { sup[2048 + tid] = 0; sel[2048 + tid] = 0; }

    // --- 3. sort on 16 warps; sorter-only named barriers ---
    if (sorter) {
        reg_stages<1 >(e, tid, lane, 2);
        reg_stages<2 >(e, tid, lane, 4);
        reg_stages<4 >(e, tid, lane, 8);
        reg_stages<8 >(e, tid, lane, 16);
        reg_stages<16>(e, tid, lane, 32);
        reg_stages<32>(e, tid, lane, 64);
        reg_stages<64>(e, tid, lane, 128);

#pragma unroll 1
        for (int k = 256; k <= MAIN; k <<= 1) {
#pragma unroll
            for (int v = 0; v < 4; v++) mkey[tid * 4 + v] = e[v];
            BARS();
            if (k == 256) {
                single128(mkey, k, tid);
            } else if (k == 512) {
                pass2(mkey, k, 128, 7, tid);
            } else if (k == 1024) {
                pass2(mkey, k, 256, 8, tid);
                BARS();
                single128(mkey, k, tid);
            } else {
                pass2(mkey, k, 512, 9, tid);
                BARS();
                pass2(mkey, k, 128, 7, tid);
            }
            BARS();
#pragma unroll
            for (int v = 0; v < 4; v++) e[v] = mkey[tid * 4 + v];
            reg_stages<64>(e, tid, lane, k);
        }
        // publish sorted main run
#pragma unroll
        for (int v = 0; v < 4; v++) mkey[tid * 4 + v] = e[v];
    }
    __syncthreads();   // full: mkey + extra visible to everyone

    // --- 3d. rank merge with extras; fused mom build ---
    if (sorter) {
#pragma unroll
        for (int v = 0; v < 4; v++) {
            u64 x = e[v];
            int lo = 0, hiS = NEXTRA;
            while (lo < hiS) {
                int mid = (lo + hiS) >> 1;
                if (extra[mid] > x) lo = mid + 1; else hiS = mid;
            }
            int dst = tid * 4 + v + lo;
            fkey[dst] = x;
            int orig = 2079 - (int)(unsigned)(x & 0xFFFFFFFFull);
            mom[dst] = (unsigned)rr[orig] | (((unsigned)cc[orig] + 1u) << 16);
        }
    } else if (wid == 16) {
        u64 x = extra[lane];
        int lo = 0, hiS = MAIN;
        while (lo < hiS) {
            int mid = (lo + hiS) >> 1;
            if (mkey[mid] > x) lo = mid + 1; else hiS = mid;
        }
        int dst = lo + lane;
        fkey[dst] = x;
        int orig = 2079 - (int)(unsigned)(x & 0xFFFFFFFFull);
        mom[dst] = (unsigned)rr[orig] | (((unsigned)cc[orig] + 1u) << 16);
    }
    __syncthreads();

    // --- 4. cache moments in registers ---
    unsigned momA = mom[tid];
    unsigned momB = mom[tid + 1024];
    unsigned momC = (wid == 0) ? mom[2048 + tid] : 0u;

    // --- 5. NMS: 1 barrier per pivot, redundant per-warp bookkeeping ---
    // each warp maintains its own copy of the cumulative suppressed bitmap:
    // lane l holds cum word l (A: words 0..31, B: words 32..63), cumC broadcast.
    unsigned cumA = 0, cumB = 0, cumC = 0;
    int piv = 0;   // first pivot is always 0 (uniform across block)
#pragma unroll 1
    for (int iter = 0; iter < TOPK; iter++) {
        if (piv < 0) break;   // uniform: all warps compute identical piv
        unsigned* wbuf = (iter & 1) ? words1 : words0;

        unsigned mp = mom[piv];   // LDS broadcast
        int s_i = (int)(mp & 0xffffu), e_i = (int)(mp >> 16);

        bool m1p, m2p, m3p = false;
        {
            int sj = (int)(momA & 0xffffu), ej = (int)(momA >> 16);
            int inter = min(ej, e_i) - max(sj, s_i);
            int uni   = max(ej, e_i) - min(sj, s_i);
            m1p = (2 * inter > uni) && (tid > piv);
        }
        {
            int sj = (int)(momB & 0xffffu), ej = (int)(momB >> 16);
            int inter = min(ej, e_i) - max(sj, s_i);
            int uni   = max(ej, e_i) - min(sj, s_i);
            m2p = (2 * inter > uni) && (tid + 1024 > piv);
        }
        unsigned b1 = __ballot_sync(0xffffffffu, m1p);
        unsigned b2 = __ballot_sync(0xffffffffu, m2p);
        if (lane == 0) { wbuf[wid] = b1; wbuf[32 + wid] = b2; }
        unsigned b3 = 0;
        if (wid == 0) {
            int sj = (int)(momC & 0xffffu), ej = (int)(momC >> 16);
            int inter = min(ej, e_i) - max(sj, s_i);
            int uni   = max(ej, e_i) - min(sj, s_i);
            m3p = (2 * inter > uni) && (2048 + tid > piv);
            b3 = __ballot_sync(0xffffffffu, m3p);
            if (lane == 0) wbuf[64] = b3;
        }
        __syncthreads();

        // every warp: read words, packed popc reductions for prefixes
        unsigned wA = wbuf[lane], wB = wbuf[32 + lane], wC = wbuf[64];
        unsigned packAll = __popc(wA) | (__popc(wB) << 16);
        unsigned packLT  = (lane < wid) ? packAll : 0u;
        unsigned sumLT  = bfly_sum(packLT);
        unsigned sumAll = bfly_sum(packAll);
        int pfxA = (int)(sumLT & 0xffffu);
        int totA = (int)(sumAll & 0xffffu);
        int pfxB = totA + (int)(sumLT >> 16);
        int totB = (int)(sumAll >> 16);

        // immediate sup/sel writes (read only after final barrier)
        if (m1p) { int rank = pfxA + __popc(b1 & lm_le); sup[tid] = 1;        if (rank <= NEIGHBOR) sel[tid] = 1; }
        if (m2p) { int rank = pfxB + __popc(b2 & lm_le); sup[tid + 1024] = 1; if (rank <= NEIGHBOR) sel[tid + 1024] = 1; }
        if (m3p) { int rank = totA + totB + __popc(b3 & lm_le); sup[2048 + tid] = 1; if (rank <= NEIGHBOR) sel[2048 + tid] = 1; }
        if (tid == 0) { sup[piv] = 1; sel[piv] = 1; }

        // cum update (identical in every warp)
        cumA |= wA; cumB |= wB; cumC |= wC;
        {
            int pw = piv >> 5, pb = piv & 31;
            if (pw < 32)      { if (lane == pw)      cumA |= (1u << pb); }
            else if (pw < 64) { if (lane == pw - 32) cumB |= (1u << pb); }
            else              { cumC |= (1u << pb); }
        }
        // next pivot (redundant per warp; deterministic)
        {
            unsigned fA = ~cumA;
            unsigned balA = __ballot_sync(0xffffffffu, fA != 0u);
            int npiv = -1;
            if (balA) {
                int l0 = __ffs(balA) - 1;
                unsigned f = __shfl_sync(0xffffffffu, fA, l0);
                npiv = l0 * 32 + __ffs(f) - 1;
            } else {
                unsigned fB = ~cumB;
                unsigned balB = __ballot_sync(0xffffffffu, fB != 0u);
                if (balB) {
                    int l0 = __ffs(balB) - 1;
                    unsigned f = __shfl_sync(0xffffffffu, fB, l0);
                    npiv = (32 + l0) * 32 + __ffs(f) - 1;
                } else {
                    unsigned fC = (~cumC) & 0x7fffffffu;   // exclude j = 2079
                    if (fC) npiv = 2048 + __ffs(fC) - 1;
                }
            }
            piv = npiv;
        }
    }
    __syncthreads();   // sup/sel visible for compaction

    // --- 6. fused dual compaction, packed counts, 2 barriers ---
    bool pU[3], pS[3]; int lU = 0, lS = 0;
#pragma unroll
    for (int u = 0; u < 3; u++) {
        int j = 3 * tid + u;
        bool valid = (j < MV);
        unsigned char sv = valid ? sup[j] : 1;
        unsigned char ev = valid ? sel[j] : 0;
        pU[u] = valid && (sv == 0);
        pS[u] = valid && (ev != 0);
        lU += (int)pU[u]; lS += (int)pS[u];
    }
    unsigned xP = (unsigned)lU | ((unsigned)lS << 16);
#pragma unroll
    for (int d = 1; d < 32; d <<= 1) {
        unsigned y = __shfl_up_sync(0xffffffffu, xP, d);
        if (lane >= d) xP += y;
    }
    if (lane == 31) wsum[wid] = xP;   // packed inclusive warp totals
    __syncthreads();
    unsigned wt = wsum[lane];
    unsigned sLT  = bfly_sum((lane < wid) ? wt : 0u);
    unsigned sAll = bfly_sum(wt);
    int baseU = (int)(sLT & 0xffffu) + (int)(xP & 0xffffu) - lU;
    int baseS = (int)(sLT >> 16)     + (int)(xP >> 16)     - lS;
    int nUnsup = (int)(sAll & 0xffffu);
    int nSel   = (int)(sAll >> 16);
#pragma unroll
    for (int u = 0; u < 3; u++) {
        if (pU[u]) unsupIdx[baseU++] = (unsigned short)(3 * tid + u);
        if (pS[u]) selIdx[baseS++]   = (unsigned short)(3 * tid + u);
    }
    __syncthreads();

    // --- 7. final index assembly + small outputs ---
    float* feat = out;
    float* se   = out + (size_t)NB * KOUT * DFEAT;
    float* off  = se  + (size_t)NB * KOUT * 2;
    float* sc   = off + (size_t)NB * KOUT * 2;

    if (tid < KOUT) {
        int k = tid;
        int val;
        if (k < NEGATIVE) {
            int pos = nUnsup - 1 - k;
            if (pos < 0) pos = 0;
            val = (pos < nUnsup) ? (int)unsupIdx[pos] : (MV - 1);
        } else {
            int p = k - NEGATIVE;
            int pad = TOTAL - nSel;
            if (p < pad) {
                val = (p < nUnsup) ? (int)unsupIdx[p] : (MV - 1);
            } else {
                val = (int)selIdx[p - pad];
            }
        }
        int orig = 2079 - (int)(unsigned)(fkey[val] & 0xFFFFFFFFull);
        int r = rr[orig], c = cc[orig];
        fr[k] = r; fc[k] = c;

        size_t o = (size_t)b * KOUT + k;
        se[o * 2 + 0] = (float)r;
        se[o * 2 + 1] = (float)(c + 1);
        size_t cell = ((size_t)b * NN + r) * NN + c;
        off[o * 2 + 0] = offset_gt[cell * 2 + 0];
        off[o * 2 + 1] = offset_gt[cell * 2 + 1];
        sc[o] = tmap[cell];
    }
    __syncthreads();

    // --- 8. feature gather (float4) ---
    const float4* src = (const float4*)map2d;
    float4* dst = (float4*)feat;
    const int VEC = DFEAT / 4;   // 128
    for (int t = tid; t < KOUT * VEC; t += NT) {
        int k = t >> 7;
        int d = t & (VEC - 1);
        int r = fr[k], c = fc[k];
        dst[((size_t)b * KOUT + k) * VEC + d] =
            src[(((size_t)b * NN + r) * NN + c) * VEC + d];
    }
}

extern "C" void kernel_launch(void* const* d_in, const int* in_sizes, int n_in,
                              void* d_out, int out_size) {
    const float* score_pred = (const float*)d_in[0];
    // d_in[1] = map2d_mask (deterministic triu(ones)) — computed analytically
    const float* map2d      = (const float*)d_in[2];
    const float* offset_gt  = (const float*)d_in[3];
    const float* tmap       = (const float*)d_in[4];
    float* out = (float*)d_out;

    cudaFuncSetAttribute(aps_kernel, cudaFuncAttributeMaxDynamicSharedMemorySize,
                         SMEM_BYTES);
    aps_kernel<<<NB, NT, SMEM_BYTES>>>(score_pred, map2d, offset_gt, tmap, out);
}